// round 10
// baseline (speedup 1.0000x reference)
#include <cuda_runtime.h>
#include <cuda_fp16.h>
#include <cstdint>

// Problem constants
#define NE       1024   // experts
#define NB       1024   // batch
#define NH       64     // hidden width
#define WARPS    8
#define THREADS  256
#define RPW      128    // rows per warp  (NB / WARPS)
#define CHUNKS   8      // m16 chunks per warp (RPW / 16)
#define LDA      72     // padded halves per SMEM row (144 B -> conflict-free ldmatrix)

struct Smem {
    __half Wt[NH][LDA];             // 9216 B : Wt[o][j] = 0.5 * W2[j][o]  (pre-halved!)
    __half A[WARPS][16][LDA];       // 18432 B: per-warp fp16 h tile
    float  raw[WARPS][2][16][NH];   // 65536 B: per-warp double-buffered raw noise
    float  b2s[NH];
    float  W3s[NH];
};

static __device__ __forceinline__ uint32_t smem_u32(const void* p) {
    uint32_t a;
    asm("{ .reg .u64 t; cvta.to.shared.u64 t, %1; cvt.u32.u64 %0, t; }"
        : "=r"(a) : "l"(p));
    return a;
}

// h = sigmoid(4u-2) = 0.5 + 0.5*tanh(2u-1): one MUFU.TANH per 2 elements.
static __device__ __forceinline__ uint32_t sig2_h(float a, float b) {
    __half2 t = __floats2half2_rn(2.0f * a - 1.0f, 2.0f * b - 1.0f);
    uint32_t ti = *(uint32_t*)&t, to;
    asm("tanh.approx.f16x2 %0, %1;" : "=r"(to) : "r"(ti));
    __half2 th = *(__half2*)&to;
    __half2 hv = __hfma2(th, __half2half2(__float2half(0.5f)),
                             __half2half2(__float2half(0.5f)));
    return *(uint32_t*)&hv;
}

// packed epilogue tanh: (c0,c1) fp32 -> tanh in f16x2 -> fp32 pair (1 MUFU / 2 elems)
static __device__ __forceinline__ float2 tanh2_f16(float a, float b) {
    __half2 t = __floats2half2_rn(a, b);
    uint32_t ti = *(uint32_t*)&t, to;
    asm("tanh.approx.f16x2 %0, %1;" : "=r"(to) : "r"(ti));
    return __half22float2(*(__half2*)&to);
}

static __device__ __forceinline__ void cp_async16(uint32_t dst, const void* src) {
    asm volatile("cp.async.cg.shared.global [%0], [%1], 16;"
                 :: "r"(dst), "l"(src) : "memory");
}
static __device__ __forceinline__ void cp_commit() {
    asm volatile("cp.async.commit_group;" ::: "memory");
}
template <int N>
static __device__ __forceinline__ void cp_wait() {
    asm volatile("cp.async.wait_group %0;" :: "n"(N) : "memory");
}

static __device__ __forceinline__ void ldsm_x4(uint32_t* r, uint32_t addr) {
    asm volatile("ldmatrix.sync.aligned.m8n8.x4.shared.b16 {%0,%1,%2,%3}, [%4];"
                 : "=r"(r[0]), "=r"(r[1]), "=r"(r[2]), "=r"(r[3]) : "r"(addr) : "memory");
}
static __device__ __forceinline__ void ldsm_x2(uint32_t& b0, uint32_t& b1,
                                               uint32_t addr) {
    asm volatile("ldmatrix.sync.aligned.m8n8.x2.shared.b16 {%0,%1}, [%2];"
                 : "=r"(b0), "=r"(b1) : "r"(addr) : "memory");
}
static __device__ __forceinline__ void mma16816(float& c0, float& c1, float& c2,
                                                float& c3, const uint32_t* a,
                                                uint32_t b0, uint32_t b1) {
    asm volatile(
        "mma.sync.aligned.m16n8k16.row.col.f32.f16.f16.f32 "
        "{%0,%1,%2,%3}, {%4,%5,%6,%7}, {%8,%9}, {%0,%1,%2,%3};"
        : "+f"(c0), "+f"(c1), "+f"(c2), "+f"(c3)
        : "r"(a[0]), "r"(a[1]), "r"(a[2]), "r"(a[3]), "r"(b0), "r"(b1));
}

// ---------------------------------------------------------------------------
// One block = one expert; warp w owns rows [w*128, w*128+128), 8 m16 chunks.
// cp.async.cg prefetches chunk ch+1 raw into double-buffered SMEM while chunk
// ch computes. Wt/b2 are staged PRE-HALVED so the MMA result is already the
// tanh argument ((z+b2)/2): epilogue = pack pair -> tanh.f16x2 -> 2 FFMA.
// ---------------------------------------------------------------------------
__global__ __launch_bounds__(THREADS, 2)
void golem_hmma_kernel(const float* __restrict__ noise,   // [E, B, H]
                       const float* __restrict__ W2,      // [E, H, H]
                       const float* __restrict__ b2,      // [E, H]
                       const float* __restrict__ W3,      // [E, H]
                       const float* __restrict__ b3,      // [E]
                       const float* __restrict__ T,       // [B]
                       const float* __restrict__ alpha,
                       const float* __restrict__ beta,
                       const float* __restrict__ bias,
                       float* __restrict__ out)           // [B,E] + [B]
{
    extern __shared__ char smem_raw_bytes[];
    Smem& s = *(Smem*)smem_raw_bytes;

    const int e   = blockIdx.x;
    const int tid = threadIdx.x;
    const int w   = tid >> 5;
    const int l   = tid & 31;

    // T_embed piggybacks on block 0
    if (e == 0) {
        float inva = __fdividef(1.0f, alpha[0]);
        float be = beta[0], bi = bias[0];
        for (int i = tid; i < NB; i += THREADS)
            out[(size_t)NB * NE + i] = inva * cosf(be * T[i] + bi);
    }

    // Stage W2[e]/2 transposed -> Wt[o][j] fp16  (pre-halved for tanh arg)
    const float* W2e = W2 + (size_t)e * NH * NH;
    for (int i = tid; i < NH * NH; i += THREADS) {
        int j = i >> 6, o = i & 63;
        s.Wt[o][j] = __float2half_rn(0.5f * W2e[i]);
    }
    if (tid < NH) {
        s.b2s[tid] = b2[(size_t)e * NH + tid];
        s.W3s[tid] = W3[(size_t)e * NH + tid];
    }
    __syncthreads();

    // Epilogue constants for cols o = n*8 + 2*(l&3) + {0,1}:
    //   sigmoid(z+b2) = 0.5 + 0.5*tanh((z+b2)/2); MMA yields z/2, init c = b2/2.
    //   acc = sum_o (W3[o]/2)*tanh(c_o) + sum_o W3[o]/2
    float   pw3h[16];        // W3/2
    float   w3base = 0.0f;
    float2  pb2h[8];         // b2/2 pairs (fp32: init accumulators)
    #pragma unroll
    for (int n = 0; n < 8; n++) {
        int o = n * 8 + 2 * (l & 3);
        pw3h[2 * n]     = 0.5f * s.W3s[o];
        pw3h[2 * n + 1] = 0.5f * s.W3s[o + 1];
        w3base += pw3h[2 * n] + pw3h[2 * n + 1];
        pb2h[n] = make_float2(0.5f * s.b2s[o], 0.5f * s.b2s[o + 1]);
    }
    const float b3e = b3[e];

    const uint32_t aBase  = smem_u32(&s.A[w][0][0]);
    const uint32_t wtBase = smem_u32(&s.Wt[0][0]);
    const uint32_t aLd = aBase + (uint32_t)(l & 15) * (LDA * 2) + (uint32_t)(l >> 4) * 16;
    const uint32_t bLd = wtBase + (uint32_t)(l & 7) * (LDA * 2) + (uint32_t)((l >> 3) & 1) * 16;

    // ---- hoist B fragments: constant per expert, loaded once ----
    uint32_t bf[8][4][2];
    #pragma unroll
    for (int n = 0; n < 8; n++)
        #pragma unroll
        for (int ks = 0; ks < 4; ks++)
            ldsm_x2(bf[n][ks][0], bf[n][ks][1],
                    bLd + (uint32_t)n * 8 * (LDA * 2) + (uint32_t)ks * 32);

    // Coalesced mapping: lane l -> sub-row (l>>4), float col (l&15)*4
    const float* nbase = noise + ((size_t)e * NB + (size_t)w * RPW) * NH;
    const float* gsrc  = nbase + (size_t)(l >> 4) * NH + (l & 15) * 4;
    const uint32_t rawL0 = smem_u32(&s.raw[w][0][l >> 4][(l & 15) * 4]);
    const uint32_t rawL1 = smem_u32(&s.raw[w][1][l >> 4][(l & 15) * 4]);
    uint2* const cdst = (uint2*)((__half*)&s.A[w][0][0] + (l >> 4) * LDA + (l & 15) * 4);

    auto prefetch = [&](int ch, uint32_t rawDst) {
        const float* g = gsrc + (size_t)ch * 16 * NH;
        #pragma unroll
        for (int i = 0; i < 8; i++)
            cp_async16(rawDst + (uint32_t)(2 * i) * (NH * 4),
                       g + (size_t)(2 * i) * NH);
        cp_commit();
    };

    // ---- pipelined main loop ----
    prefetch(0, rawL0);

    #pragma unroll 1
    for (int ch = 0; ch < CHUNKS; ch++) {
        const uint32_t rawSrc = (ch & 1) ? rawL1 : rawL0;
        if (ch + 1 < CHUNKS) {
            prefetch(ch + 1, ((ch + 1) & 1) ? rawL1 : rawL0);
            cp_wait<1>();    // chunk ch landed; ch+1 still in flight
        } else {
            cp_wait<0>();
        }
        __syncwarp();        // also orders prev ldsm reads vs our A stores

        // ---- convert: batch ALL 8 LDS first (independent, pipelined), ----
        // ---- then sigmoid+pack+store — no serial LDS->MUFU chain.      ----
        float4 v[8];
        #pragma unroll
        for (int i = 0; i < 8; i++)
            asm volatile("ld.shared.v4.f32 {%0,%1,%2,%3}, [%4];"
                         : "=f"(v[i].x), "=f"(v[i].y), "=f"(v[i].z), "=f"(v[i].w)
                         : "r"(rawSrc + (uint32_t)(2 * i) * (NH * 4)));
        #pragma unroll
        for (int i = 0; i < 8; i++) {
            uint2 pk;
            pk.x = sig2_h(v[i].x, v[i].y);
            pk.y = sig2_h(v[i].z, v[i].w);
            cdst[(size_t)(2 * i) * (LDA / 4)] = pk;
        }
        __syncwarp();

        // ---- A fragments: 4 K-steps ----
        uint32_t a[4][4];
        #pragma unroll
        for (int ks = 0; ks < 4; ks++)
            ldsm_x4(a[ks], aLd + (uint32_t)ks * 32);

        // ---- GEMM + packed-tanh epilogue per n-tile (B from registers) ----
        float acc0 = w3base, acc1 = w3base;
        #pragma unroll
        for (int n = 0; n < 8; n++) {
            float c0 = pb2h[n].x, c1 = pb2h[n].y;
            float c2 = pb2h[n].x, c3 = pb2h[n].y;
            #pragma unroll
            for (int ks = 0; ks < 4; ks++)
                mma16816(c0, c1, c2, c3, a[ks], bf[n][ks][0], bf[n][ks][1]);
            float2 t01 = tanh2_f16(c0, c1);
            float2 t23 = tanh2_f16(c2, c3);
            acc0 += t01.x * pw3h[2 * n] + t01.y * pw3h[2 * n + 1];
            acc1 += t23.x * pw3h[2 * n] + t23.y * pw3h[2 * n + 1];
        }

        // quad reduce over (l&3)
        acc0 += __shfl_xor_sync(0xffffffffu, acc0, 1);
        acc0 += __shfl_xor_sync(0xffffffffu, acc0, 2);
        acc1 += __shfl_xor_sync(0xffffffffu, acc1, 1);
        acc1 += __shfl_xor_sync(0xffffffffu, acc1, 2);

        if ((l & 3) == 0) {
            int r = w * RPW + ch * 16 + (l >> 2);
            out[(size_t)r * NE + e]       = acc0 + b3e;
            out[(size_t)(r + 8) * NE + e] = acc1 + b3e;
        }
    }
}

// ---------------------------------------------------------------------------
// kernel_launch — inputs: 0:T 1:noise 2:W1(dead) 3:W2 4:b2 5:W3 6:b3
//                          7:alpha 8:beta 9:bias.  Output fp32: B_mat[B,E] + T_embed[B]
// ---------------------------------------------------------------------------
extern "C" void kernel_launch(void* const* d_in, const int* in_sizes, int n_in,
                              void* d_out, int out_size)
{
    const float* T     = (const float*)d_in[0];
    const float* noise = (const float*)d_in[1];
    const float* W2    = (const float*)d_in[3];
    const float* b2    = (const float*)d_in[4];
    const float* W3    = (const float*)d_in[5];
    const float* b3    = (const float*)d_in[6];
    const float* alpha = (const float*)d_in[7];
    const float* beta  = (const float*)d_in[8];
    const float* bias  = (const float*)d_in[9];

    cudaFuncSetAttribute(golem_hmma_kernel,
                         cudaFuncAttributeMaxDynamicSharedMemorySize,
                         (int)sizeof(Smem));
    golem_hmma_kernel<<<NE, THREADS, sizeof(Smem)>>>(noise, W2, b2, W3, b3,
                                                     T, alpha, beta, bias,
                                                     (float*)d_out);
}

// round 11
// speedup vs baseline: 1.2790x; 1.2790x over previous
#include <cuda_runtime.h>
#include <cuda_fp16.h>
#include <cstdint>

// Problem constants
#define NE       1024   // experts
#define NB       1024   // batch
#define NH       64     // hidden width
#define WARPS    8
#define THREADS  256
#define RPW      128    // rows per warp  (NB / WARPS)
#define CHUNKS   8      // m16 chunks per warp (RPW / 16)
#define LDA      72     // padded halves per SMEM row (144 B -> conflict-free ldmatrix)

struct Smem {
    __half   Wt[NH][LDA];              // 9216 B : Wt[o][j] = 0.5 * W2[j][o] (pre-halved)
    __half   A[WARPS][16][LDA];        // 18432 B: per-warp fp16 h tile
    float    raw[WARPS][2][8][NH];     // 32768 B: per-warp double-buffered raw half-chunks
    uint32_t bfs[8][2][32][4];         // 8192 B : B fragments [n][kspair][lane][4]
    float    b2s[NH];
    float    W3s[NH];
};

static __device__ __forceinline__ uint32_t smem_u32(const void* p) {
    uint32_t a;
    asm("{ .reg .u64 t; cvta.to.shared.u64 t, %1; cvt.u32.u64 %0, t; }"
        : "=r"(a) : "l"(p));
    return a;
}

// h = sigmoid(4u-2) = 0.5 + 0.5*tanh(2u-1): one MUFU.TANH per 2 elements.
static __device__ __forceinline__ uint32_t sig2_h(float a, float b) {
    __half2 t = __floats2half2_rn(2.0f * a - 1.0f, 2.0f * b - 1.0f);
    uint32_t ti = *(uint32_t*)&t, to;
    asm("tanh.approx.f16x2 %0, %1;" : "=r"(to) : "r"(ti));
    __half2 th = *(__half2*)&to;
    __half2 hv = __hfma2(th, __half2half2(__float2half(0.5f)),
                             __half2half2(__float2half(0.5f)));
    return *(uint32_t*)&hv;
}

// packed epilogue tanh: (a,b) fp32 -> tanh via f16x2 -> fp32 pair (1 MUFU / 2 elems)
static __device__ __forceinline__ float2 tanh2_f16(float a, float b) {
    __half2 t = __floats2half2_rn(a, b);
    uint32_t ti = *(uint32_t*)&t, to;
    asm("tanh.approx.f16x2 %0, %1;" : "=r"(to) : "r"(ti));
    return __half22float2(*(__half2*)&to);
}

static __device__ __forceinline__ void cp_async16(uint32_t dst, const void* src) {
    asm volatile("cp.async.cg.shared.global [%0], [%1], 16;"
                 :: "r"(dst), "l"(src) : "memory");
}
static __device__ __forceinline__ void cp_commit() {
    asm volatile("cp.async.commit_group;" ::: "memory");
}
template <int N>
static __device__ __forceinline__ void cp_wait() {
    asm volatile("cp.async.wait_group %0;" :: "n"(N) : "memory");
}

static __device__ __forceinline__ void ldsm_x4(uint32_t* r, uint32_t addr) {
    asm volatile("ldmatrix.sync.aligned.m8n8.x4.shared.b16 {%0,%1,%2,%3}, [%4];"
                 : "=r"(r[0]), "=r"(r[1]), "=r"(r[2]), "=r"(r[3]) : "r"(addr) : "memory");
}
static __device__ __forceinline__ void ldsm_x2(uint32_t& b0, uint32_t& b1,
                                               uint32_t addr) {
    asm volatile("ldmatrix.sync.aligned.m8n8.x2.shared.b16 {%0,%1}, [%2];"
                 : "=r"(b0), "=r"(b1) : "r"(addr) : "memory");
}
static __device__ __forceinline__ void mma16816(float& c0, float& c1, float& c2,
                                                float& c3, const uint32_t* a,
                                                uint32_t b0, uint32_t b1) {
    asm volatile(
        "mma.sync.aligned.m16n8k16.row.col.f32.f16.f16.f32 "
        "{%0,%1,%2,%3}, {%4,%5,%6,%7}, {%8,%9}, {%0,%1,%2,%3};"
        : "+f"(c0), "+f"(c1), "+f"(c2), "+f"(c3)
        : "r"(a[0]), "r"(a[1]), "r"(a[2]), "r"(a[3]), "r"(b0), "r"(b1));
}

// ---------------------------------------------------------------------------
// One block = one expert. B fragments live in an 8KB SMEM table (identical for
// all warps -> built once by warp 0), freeing 56 regs/thread so 3 CTAs/SM fit.
// cp.async prefetches 8-row half-chunks, double-buffered per warp.
// ---------------------------------------------------------------------------
__global__ __launch_bounds__(THREADS, 3)
void golem_hmma_kernel(const float* __restrict__ noise,   // [E, B, H]
                       const float* __restrict__ W2,      // [E, H, H]
                       const float* __restrict__ b2,      // [E, H]
                       const float* __restrict__ W3,      // [E, H]
                       const float* __restrict__ b3,      // [E]
                       const float* __restrict__ T,       // [B]
                       const float* __restrict__ alpha,
                       const float* __restrict__ beta,
                       const float* __restrict__ bias,
                       float* __restrict__ out)           // [B,E] + [B]
{
    extern __shared__ char smem_raw_bytes[];
    Smem& s = *(Smem*)smem_raw_bytes;

    const int e   = blockIdx.x;
    const int tid = threadIdx.x;
    const int w   = tid >> 5;
    const int l   = tid & 31;

    // T_embed piggybacks on block 0
    if (e == 0) {
        float inva = __fdividef(1.0f, alpha[0]);
        float be = beta[0], bi = bias[0];
        for (int i = tid; i < NB; i += THREADS)
            out[(size_t)NB * NE + i] = inva * cosf(be * T[i] + bi);
    }

    // Stage W2[e]/2 transposed -> Wt[o][j] fp16 (pre-halved for tanh arg)
    const float* W2e = W2 + (size_t)e * NH * NH;
    for (int i = tid; i < NH * NH; i += THREADS) {
        int j = i >> 6, o = i & 63;
        s.Wt[o][j] = __float2half_rn(0.5f * W2e[i]);
    }
    if (tid < NH) {
        s.b2s[tid] = b2[(size_t)e * NH + tid];
        s.W3s[tid] = W3[(size_t)e * NH + tid];
    }
    __syncthreads();

    // Warp 0 builds the B-fragment table (identical for every warp)
    if (w == 0) {
        const uint32_t wtBase = smem_u32(&s.Wt[0][0]);
        const uint32_t bLd = wtBase + (uint32_t)(l & 7) * (LDA * 2)
                           + (uint32_t)((l >> 3) & 1) * 16;
        #pragma unroll
        for (int n = 0; n < 8; n++)
            #pragma unroll
            for (int ks = 0; ks < 4; ks++) {
                uint32_t b0, b1;
                ldsm_x2(b0, b1, bLd + (uint32_t)n * 8 * (LDA * 2) + (uint32_t)ks * 32);
                s.bfs[n][ks >> 1][l][(ks & 1) * 2 + 0] = b0;
                s.bfs[n][ks >> 1][l][(ks & 1) * 2 + 1] = b1;
            }
    }
    __syncthreads();

    // Epilogue constants for cols o = n*8 + 2*(l&3) + {0,1}:
    //   sigmoid(z+b2) = 0.5 + 0.5*tanh((z+b2)/2); MMA yields z/2, init c = b2/2.
    float   pw3h[16];        // W3/2
    float   w3base = 0.0f;
    __half2 pb2h[8];         // b2/2 pairs
    #pragma unroll
    for (int n = 0; n < 8; n++) {
        int o = n * 8 + 2 * (l & 3);
        pw3h[2 * n]     = 0.5f * s.W3s[o];
        pw3h[2 * n + 1] = 0.5f * s.W3s[o + 1];
        w3base += pw3h[2 * n] + pw3h[2 * n + 1];
        pb2h[n] = __floats2half2_rn(0.5f * s.b2s[o], 0.5f * s.b2s[o + 1]);
    }
    const float b3e = b3[e];

    const uint32_t aBase = smem_u32(&s.A[w][0][0]);
    const uint32_t aLd = aBase + (uint32_t)(l & 15) * (LDA * 2) + (uint32_t)(l >> 4) * 16;
    // per-lane B table pointer: bfs[n][kp][l][0..3] -> uint4 index (n*2+kp)*32 + l
    const uint4* const bfp = (const uint4*)&s.bfs[0][0][0][0] + l;

    // Coalesced mapping: lane l -> sub-row (l>>4), float col (l&15)*4
    const float* nbase = noise + ((size_t)e * NB + (size_t)w * RPW) * NH;
    const float* gsrc  = nbase + (size_t)(l >> 4) * NH + (l & 15) * 4;
    const uint32_t rawL0 = smem_u32(&s.raw[w][0][l >> 4][(l & 15) * 4]);
    const uint32_t rawL1 = smem_u32(&s.raw[w][1][l >> 4][(l & 15) * 4]);

    // prefetch one 8-row half-chunk (4 x 16B per lane)
    auto prefetch_half = [&](int hc, uint32_t rawDst) {
        const float* g = gsrc + (size_t)hc * 8 * NH;
        #pragma unroll
        for (int i = 0; i < 4; i++)
            cp_async16(rawDst + (uint32_t)(2 * i) * (NH * 4),
                       g + (size_t)(2 * i) * NH);
        cp_commit();
    };
    // convert one half-chunk into A rows [hb*8, hb*8+8)
    auto convert_half = [&](uint32_t rawSrc, int hb) {
        uint2* cd = (uint2*)((__half*)&s.A[w][0][0]
                             + (hb * 8 + (l >> 4)) * LDA + (l & 15) * 4);
        #pragma unroll
        for (int i = 0; i < 4; i++) {
            float4 v;
            asm volatile("ld.shared.v4.f32 {%0,%1,%2,%3}, [%4];"
                         : "=f"(v.x), "=f"(v.y), "=f"(v.z), "=f"(v.w)
                         : "r"(rawSrc + (uint32_t)(2 * i) * (NH * 4)));
            uint2 pk;
            pk.x = sig2_h(v.x, v.y);
            pk.y = sig2_h(v.z, v.w);
            cd[(size_t)(2 * i) * (LDA / 4)] = pk;
        }
    };

    // ---- pipelined main loop (half-chunk granularity prefetch) ----
    prefetch_half(0, rawL0);
    prefetch_half(1, rawL1);

    #pragma unroll 1
    for (int ch = 0; ch < CHUNKS; ch++) {
        cp_wait<1>();            // half-chunk 2ch landed
        __syncwarp();
        convert_half(rawL0, 0);
        if (2 * ch + 2 < 2 * CHUNKS) prefetch_half(2 * ch + 2, rawL0);
        else                         cp_commit();

        cp_wait<1>();            // half-chunk 2ch+1 landed
        __syncwarp();
        convert_half(rawL1, 1);
        if (2 * ch + 3 < 2 * CHUNKS) prefetch_half(2 * ch + 3, rawL1);
        else                         cp_commit();
        __syncwarp();

        // ---- A fragments: 4 K-steps ----
        uint32_t a[4][4];
        #pragma unroll
        for (int ks = 0; ks < 4; ks++)
            ldsm_x4(a[ks], aLd + (uint32_t)ks * 32);

        // ---- GEMM + packed-tanh epilogue (B from SMEM table, 2 LDS.128/n) ----
        float acc0 = w3base, acc1 = w3base;
        #pragma unroll
        for (int n = 0; n < 8; n++) {
            float2 b2p = __half22float2(pb2h[n]);
            float c0 = b2p.x, c1 = b2p.y, c2 = b2p.x, c3 = b2p.y;
            uint4 bA = bfp[(n * 2 + 0) * 32];
            uint4 bB = bfp[(n * 2 + 1) * 32];
            mma16816(c0, c1, c2, c3, a[0], bA.x, bA.y);
            mma16816(c0, c1, c2, c3, a[1], bA.z, bA.w);
            mma16816(c0, c1, c2, c3, a[2], bB.x, bB.y);
            mma16816(c0, c1, c2, c3, a[3], bB.z, bB.w);
            float2 t01 = tanh2_f16(c0, c1);
            float2 t23 = tanh2_f16(c2, c3);
            acc0 += t01.x * pw3h[2 * n] + t01.y * pw3h[2 * n + 1];
            acc1 += t23.x * pw3h[2 * n] + t23.y * pw3h[2 * n + 1];
        }

        // quad reduce over (l&3)
        acc0 += __shfl_xor_sync(0xffffffffu, acc0, 1);
        acc0 += __shfl_xor_sync(0xffffffffu, acc0, 2);
        acc1 += __shfl_xor_sync(0xffffffffu, acc1, 1);
        acc1 += __shfl_xor_sync(0xffffffffu, acc1, 2);

        if ((l & 3) == 0) {
            int r = w * RPW + ch * 16 + (l >> 2);
            out[(size_t)r * NE + e]       = acc0 + b3e;
            out[(size_t)(r + 8) * NE + e] = acc1 + b3e;
        }
    }
}

// ---------------------------------------------------------------------------
// kernel_launch — inputs: 0:T 1:noise 2:W1(dead) 3:W2 4:b2 5:W3 6:b3
//                          7:alpha 8:beta 9:bias.  Output fp32: B_mat[B,E] + T_embed[B]
// ---------------------------------------------------------------------------
extern "C" void kernel_launch(void* const* d_in, const int* in_sizes, int n_in,
                              void* d_out, int out_size)
{
    const float* T     = (const float*)d_in[0];
    const float* noise = (const float*)d_in[1];
    const float* W2    = (const float*)d_in[3];
    const float* b2    = (const float*)d_in[4];
    const float* W3    = (const float*)d_in[5];
    const float* b3    = (const float*)d_in[6];
    const float* alpha = (const float*)d_in[7];
    const float* beta  = (const float*)d_in[8];
    const float* bias  = (const float*)d_in[9];

    cudaFuncSetAttribute(golem_hmma_kernel,
                         cudaFuncAttributeMaxDynamicSharedMemorySize,
                         (int)sizeof(Smem));
    golem_hmma_kernel<<<NE, THREADS, sizeof(Smem)>>>(noise, W2, b2, W3, b3,
                                                     T, alpha, beta, bias,
                                                     (float*)d_out);
}